// round 2
// baseline (speedup 1.0000x reference)
#include <cuda_runtime.h>
#include <cstddef>
#include <cstdint>

#define Bc 48
#define Wn 8192
#define Fc 64
#define Dc 128
#define GRAM_CHUNKS 32

typedef unsigned long long ull;

// Scratch (no runtime allocation allowed)
__device__ float g_gram_part[Bc * GRAM_CHUNKS * Fc * Fc]; // 25.2 MB
__device__ float g_gram[Bc * Fc * Fc];                    // 786 KB
__device__ float g_h[(size_t)Bc * Wn * Fc];               // 100.7 MB

// ---------------------------------------------------------------------------
// packed f32x2 helpers (FFMA2 — only reachable via PTX)
// ---------------------------------------------------------------------------
__device__ __forceinline__ ull pack2(float a, float b) {
    ull r;
    asm("mov.b64 %0, {%1, %2};" : "=l"(r) : "r"(__float_as_uint(a)), "r"(__float_as_uint(b)));
    return r;
}
__device__ __forceinline__ ull dup2(float a) {
    ull r;
    asm("mov.b64 %0, {%1, %1};" : "=l"(r) : "r"(__float_as_uint(a)));
    return r;
}
__device__ __forceinline__ void unpack2(ull v, float& a, float& b) {
    unsigned lo, hi;
    asm("mov.b64 {%0, %1}, %2;" : "=r"(lo), "=r"(hi) : "l"(v));
    a = __uint_as_float(lo); b = __uint_as_float(hi);
}
__device__ __forceinline__ ull ffma2(ull a, ull b, ull c) {
    ull d;
    asm("fma.rn.f32x2 %0, %1, %2, %3;" : "=l"(d) : "l"(a), "l"(b), "l"(c));
    return d;
}
// broadcast 16B shared load -> two packed f32x2
__device__ __forceinline__ void lds128(unsigned addr, ull& a, ull& b) {
    asm volatile("ld.shared.v2.u64 {%0, %1}, [%2];" : "=l"(a), "=l"(b) : "r"(addr));
}

// ---------------------------------------------------------------------------
// Kernel 1: per-chunk partial Gram of row-normalized x (unchanged from R1).
// ---------------------------------------------------------------------------
__global__ void __launch_bounds__(256) gram_partial(const float* __restrict__ x) {
    const int b = blockIdx.y;
    const int chunk = blockIdx.x;
    const int rows_per_chunk = Wn / GRAM_CHUNKS; // 256
    const int w_base = chunk * rows_per_chunk;

    __shared__ float xs[64][65];
    __shared__ float sinv2[64];

    const int t = threadIdx.x;
    const int ti = t >> 4;
    const int tj = t & 15;

    float acc[4][4] = {};
    const float* xb = x + (size_t)b * Wn * Fc;

    for (int tile = 0; tile < rows_per_chunk; tile += 64) {
        for (int i = t; i < 64 * 64; i += 256) {
            int r = i >> 6, c = i & 63;
            xs[r][c] = xb[(size_t)(w_base + tile + r) * Fc + c];
        }
        __syncthreads();
        if (t < 64) {
            float s = 0.f;
            #pragma unroll
            for (int c = 0; c < 64; c++) { float v = xs[t][c]; s += v * v; }
            sinv2[t] = 1.0f / s;
        }
        __syncthreads();
        #pragma unroll 4
        for (int w = 0; w < 64; w++) {
            float s = sinv2[w];
            float vi[4], vj[4];
            #pragma unroll
            for (int a = 0; a < 4; a++) vi[a] = xs[w][ti + 16 * a] * s;
            #pragma unroll
            for (int a = 0; a < 4; a++) vj[a] = xs[w][tj + 16 * a];
            #pragma unroll
            for (int a = 0; a < 4; a++)
                #pragma unroll
                for (int c = 0; c < 4; c++) acc[a][c] += vi[a] * vj[c];
        }
        __syncthreads();
    }

    float* dst = g_gram_part + ((size_t)b * GRAM_CHUNKS + chunk) * (Fc * Fc);
    #pragma unroll
    for (int a = 0; a < 4; a++)
        #pragma unroll
        for (int c = 0; c < 4; c++)
            dst[(ti + 16 * a) * 64 + (tj + 16 * c)] = acc[a][c];
}

__global__ void __launch_bounds__(256) gram_reduce() {
    const int b = blockIdx.x;
    const int t = threadIdx.x;
    for (int i = t; i < Fc * Fc; i += 256) {
        float s = 0.f;
        #pragma unroll
        for (int c = 0; c < GRAM_CHUNKS; c++)
            s += g_gram_part[((size_t)b * GRAM_CHUNKS + c) * (Fc * Fc) + i];
        g_gram[b * Fc * Fc + i] = s;
    }
}

// ---------------------------------------------------------------------------
// Kernel H: h[b,w,f] = ctxConv(x)+ctx_b + relu(gram@seW + seb)
// lanes = w, weights broadcast, FFMA2. 2 CTAs/SM (99.8 KB smem).
// ---------------------------------------------------------------------------
// smem float offsets
#define H_GRAM 0                        // 4096
#define H_CWT  4096                     // 192*64 = 12288  (cwt[(g*3+k)*64 + f])
#define H_XT   16384                    // 64*67 = 4288    (x_t[g*67 + j], j=0..65)
#define H_SEWT 20672                    // 64*67 = 4288    (sew_t[g*67 + r])
#define H_TOTALF 24960
#define H_SMEM (H_TOTALF * 4)
// cw_pad overlay (64*97 = 6208 floats) sits at H_XT during weight transpose.

__global__ void __launch_bounds__(512, 2) h_kernel(
    const float* __restrict__ x,
    const float* __restrict__ ctx_w,
    const float* __restrict__ ctx_b,
    const float* __restrict__ seW_w,
    const float* __restrict__ seW_b)
{
    extern __shared__ float sm[];
    const int b  = blockIdx.y;
    const int w0 = blockIdx.x * 64;
    const int t  = threadIdx.x;
    const float* xb = x + (size_t)b * Wn * Fc;

    // ---- stage ctx weights: two-step transpose, two halves ----
    float* cw_pad = sm + H_XT; // overlay
    #pragma unroll
    for (int half = 0; half < 2; half++) {
        for (int i = t; i < 64 * 96; i += 512) {
            int f = i / 96, jj = i - f * 96;
            cw_pad[f * 97 + jj] = ctx_w[f * 192 + half * 96 + jj];
        }
        __syncthreads();
        for (int i = t; i < 64 * 96; i += 512) {
            int f = i & 63, jj = i >> 6;
            sm[H_CWT + (half * 96 + jj) * 64 + f] = cw_pad[f * 97 + jj];
        }
        __syncthreads();
    }
    // ---- gram, x_t, sew_t ----
    for (int i = t; i < 4096; i += 512) sm[H_GRAM + i] = g_gram[b * 4096 + i];
    for (int i = t; i < 66 * 64; i += 512) {
        int j = i >> 6, c = i & 63;
        int gr = w0 - 1 + j;
        sm[H_XT + c * 67 + j] = (gr >= 0 && gr < Wn) ? xb[(size_t)gr * Fc + c] : 0.f;
    }
    for (int i = t; i < 64 * 64; i += 512) {
        int r = i >> 6, c = i & 63;
        sm[H_SEWT + c * 67 + r] = seW_w[(size_t)(w0 + r) * Fc + c];
    }
    __syncthreads();

    // ---- main: thread = (whalf, fblk); w = whalf*32+lane, f tile = 8 ----
    const int wp = t >> 5, lane = t & 31;
    const int w  = (wp & 1) * 32 + lane;
    const int f0 = (wp >> 1) * 8;

    ull accC[4], accS[4];
    {
        float seb = seW_b[w0 + w];
        #pragma unroll
        for (int p = 0; p < 4; p++) {
            accC[p] = pack2(ctx_b[f0 + 2 * p], ctx_b[f0 + 2 * p + 1]);
            accS[p] = dup2(seb);
        }
    }

    unsigned sbase = (unsigned)__cvta_generic_to_shared(sm);
    unsigned cwt_a = sbase + (H_CWT + f0) * 4;
    unsigned gr_a  = sbase + (H_GRAM + f0) * 4;
    const float* xg = sm + H_XT + w;
    const float* sg = sm + H_SEWT + w;

    #pragma unroll 2
    for (int g = 0; g < 64; g++) {
        float x0 = xg[0], x1 = xg[1], x2 = xg[2];
        float sw = sg[0];
        xg += 67; sg += 67;

        ull px0 = dup2(x0), px1 = dup2(x1), px2 = dup2(x2), psw = dup2(sw);

        ull c0a, c0b, c0c, c0d, c1a, c1b, c1c, c1d, c2a, c2b, c2c, c2d;
        lds128(cwt_a,            c0a, c0b); lds128(cwt_a + 16,       c0c, c0d);
        lds128(cwt_a + 256,      c1a, c1b); lds128(cwt_a + 256 + 16, c1c, c1d);
        lds128(cwt_a + 512,      c2a, c2b); lds128(cwt_a + 512 + 16, c2c, c2d);
        ull ga, gb, gc, gd;
        lds128(gr_a, ga, gb); lds128(gr_a + 16, gc, gd);
        cwt_a += 768; gr_a += 256;

        accC[0] = ffma2(px0, c0a, accC[0]); accC[1] = ffma2(px0, c0b, accC[1]);
        accC[2] = ffma2(px0, c0c, accC[2]); accC[3] = ffma2(px0, c0d, accC[3]);
        accC[0] = ffma2(px1, c1a, accC[0]); accC[1] = ffma2(px1, c1b, accC[1]);
        accC[2] = ffma2(px1, c1c, accC[2]); accC[3] = ffma2(px1, c1d, accC[3]);
        accC[0] = ffma2(px2, c2a, accC[0]); accC[1] = ffma2(px2, c2b, accC[1]);
        accC[2] = ffma2(px2, c2c, accC[2]); accC[3] = ffma2(px2, c2d, accC[3]);
        accS[0] = ffma2(psw, ga, accS[0]);  accS[1] = ffma2(psw, gb, accS[1]);
        accS[2] = ffma2(psw, gc, accS[2]);  accS[3] = ffma2(psw, gd, accS[3]);
    }

    // epilogue: h = accC + relu(accS), write 8 consecutive f (two float4)
    float o[8];
    #pragma unroll
    for (int p = 0; p < 4; p++) {
        float c0, c1, s0, s1;
        unpack2(accC[p], c0, c1);
        unpack2(accS[p], s0, s1);
        o[2 * p]     = c0 + fmaxf(s0, 0.f);
        o[2 * p + 1] = c1 + fmaxf(s1, 0.f);
    }
    float* hb = g_h + ((size_t)b * Wn + w0 + w) * Fc + f0;
    *(float4*)(hb)     = make_float4(o[0], o[1], o[2], o[3]);
    *(float4*)(hb + 4) = make_float4(o[4], o[5], o[6], o[7]);
}

// ---------------------------------------------------------------------------
// Kernel O: out[b,w,d] = sum_{f,k} h[b, (w+k-1)%Wn, f] * token_w[d,f,k]
// lanes = w, weights broadcast, FFMA2. 1 CTA/SM (161 KB smem).
// ---------------------------------------------------------------------------
#define O_TWR 0                          // 192*128 = 24576 (twr[(f*3+k)*128 + d])
#define O_TWP 24576                      // 128*97  = 12416 (transpose staging)
#define O_HT  36992                      // 64*67   = 4288  (h_t[f*67 + j], j=0..65)
#define O_TOTALF 41280
#define O_SMEM (O_TOTALF * 4)

__global__ void __launch_bounds__(512, 1) out_kernel(
    const float* __restrict__ token_w,
    float* __restrict__ out)
{
    extern __shared__ float sm[];
    const int b  = blockIdx.y;
    const int w0 = blockIdx.x * 64;
    const int t  = threadIdx.x;

    // ---- stage token weights: two-step transpose, two halves ----
    float* tw_pad = sm + O_TWP;
    #pragma unroll
    for (int half = 0; half < 2; half++) {
        for (int i = t; i < 128 * 96; i += 512) {
            int d = i / 96, jj = i - d * 96;
            tw_pad[d * 97 + jj] = token_w[d * 192 + half * 96 + jj];
        }
        __syncthreads();
        for (int i = t; i < 128 * 96; i += 512) {
            int d = i & 127, jj = i >> 7;
            sm[O_TWR + (half * 96 + jj) * 128 + d] = tw_pad[d * 97 + jj];
        }
        __syncthreads();
    }
    // ---- stage h tile transposed (circular row indexing) ----
    const float* hg = g_h + (size_t)b * Wn * Fc;
    for (int i = t; i < 66 * 64; i += 512) {
        int j = i >> 6, c = i & 63;
        int gw = (w0 - 1 + j + Wn) & (Wn - 1);
        sm[O_HT + c * 67 + j] = hg[(size_t)gw * Fc + c];
    }
    __syncthreads();

    // ---- main: thread = (whalf, dblk); w = whalf*32+lane, d tile = 16 ----
    const int wp = t >> 5, lane = t & 31;
    const int w  = (wp & 1) * 32 + lane;
    const int d0 = (wp >> 1) * 16;

    ull acc[8];
    #pragma unroll
    for (int p = 0; p < 8; p++) acc[p] = 0ull;

    unsigned sbase = (unsigned)__cvta_generic_to_shared(sm);
    unsigned twr_a = sbase + (O_TWR + d0) * 4;
    const float* hp = sm + O_HT + w;

    #pragma unroll 2
    for (int f = 0; f < 64; f++) {
        float h0 = hp[0], h1 = hp[1], h2 = hp[2];
        hp += 67;
        ull ph[3] = { dup2(h0), dup2(h1), dup2(h2) };
        #pragma unroll
        for (int k = 0; k < 3; k++) {
            ull wa, wb, wc, wd, we, wf_, wg, wh;
            unsigned a = twr_a + (unsigned)k * 512;
            lds128(a,      wa, wb);
            lds128(a + 16, wc, wd);
            lds128(a + 32, we, wf_);
            lds128(a + 48, wg, wh);
            acc[0] = ffma2(ph[k], wa, acc[0]);
            acc[1] = ffma2(ph[k], wb, acc[1]);
            acc[2] = ffma2(ph[k], wc, acc[2]);
            acc[3] = ffma2(ph[k], wd, acc[3]);
            acc[4] = ffma2(ph[k], we, acc[4]);
            acc[5] = ffma2(ph[k], wf_, acc[5]);
            acc[6] = ffma2(ph[k], wg, acc[6]);
            acc[7] = ffma2(ph[k], wh, acc[7]);
        }
        twr_a += 1536;
    }

    // epilogue: 16 consecutive d per lane (four float4, sector-aligned)
    float* ob = out + ((size_t)b * Wn + w0 + w) * Dc + d0;
    #pragma unroll
    for (int q = 0; q < 4; q++) {
        float a0, a1, a2, a3;
        unpack2(acc[2 * q],     a0, a1);
        unpack2(acc[2 * q + 1], a2, a3);
        *(float4*)(ob + 4 * q) = make_float4(a0, a1, a2, a3);
    }
}

// ---------------------------------------------------------------------------
extern "C" void kernel_launch(void* const* d_in, const int* in_sizes, int n_in,
                              void* d_out, int out_size) {
    const float* x       = (const float*)d_in[0];
    const float* ctx_w   = (const float*)d_in[1];
    const float* ctx_b   = (const float*)d_in[2];
    const float* token_w = (const float*)d_in[3];
    const float* seW_w   = (const float*)d_in[4];
    const float* seW_b   = (const float*)d_in[5];
    float* out = (float*)d_out;

    cudaFuncSetAttribute(h_kernel,
                         cudaFuncAttributeMaxDynamicSharedMemorySize, H_SMEM);
    cudaFuncSetAttribute(out_kernel,
                         cudaFuncAttributeMaxDynamicSharedMemorySize, O_SMEM);

    gram_partial<<<dim3(GRAM_CHUNKS, Bc), 256>>>(x);
    gram_reduce<<<Bc, 256>>>();
    h_kernel<<<dim3(Wn / 64, Bc), 512, H_SMEM>>>(x, ctx_w, ctx_b, seW_w, seW_b);
    out_kernel<<<dim3(Wn / 64, Bc), 512, O_SMEM>>>(token_w, out);
}

// round 3
// speedup vs baseline: 1.4806x; 1.4806x over previous
#include <cuda_runtime.h>
#include <cstddef>
#include <cstdint>

#define Bc 48
#define Wn 8192
#define Fc 64
#define Dc 128
#define GRAM_CHUNKS 32

typedef unsigned long long ull;

// device scratch (no runtime allocation allowed)
__device__ float g_gram_part[Bc * GRAM_CHUNKS * Fc * Fc];
__device__ float g_gram[Bc * Fc * Fc];
__device__ float g_h[(size_t)Bc * Wn * Fc];     // 100.7 MB intermediate
__device__ float g_cwt[192 * 64];               // ctx_w transposed  [g*3+k][f]
__device__ float g_twr[192 * 128];              // token_w transposed [f*3+k][d]

// ---------------------------------------------------------------------------
// packed f32x2 helpers
// ---------------------------------------------------------------------------
__device__ __forceinline__ ull dup2(float a) {
    ull r;
    asm("mov.b64 %0, {%1, %1};" : "=l"(r) : "r"(__float_as_uint(a)));
    return r;
}
__device__ __forceinline__ void unpack2(ull v, float& a, float& b) {
    unsigned lo, hi;
    asm("mov.b64 {%0, %1}, %2;" : "=r"(lo), "=r"(hi) : "l"(v));
    a = __uint_as_float(lo); b = __uint_as_float(hi);
}
__device__ __forceinline__ ull ffma2(ull a, ull b, ull c) {
    ull d;
    asm("fma.rn.f32x2 %0, %1, %2, %3;" : "=l"(d) : "l"(a), "l"(b), "l"(c));
    return d;
}
// per-lane 16B shared load -> two packed f32x2 (pairs (w0,w1),(w2,w3))
__device__ __forceinline__ void lds128p(unsigned addr, ull& a, ull& b) {
    asm volatile("ld.shared.v2.u64 {%0, %1}, [%2];" : "=l"(a), "=l"(b) : "r"(addr));
}

// ---------------------------------------------------------------------------
// Kernel 0: one-time weight transposes (tiny)
// ---------------------------------------------------------------------------
__global__ void __launch_bounds__(256) transpose_weights(
    const float* __restrict__ ctx_w, const float* __restrict__ token_w) {
    int tid = blockIdx.x * 256 + threadIdx.x;
    int nt = gridDim.x * 256;
    for (int i = tid; i < 64 * 192; i += nt) {
        int f = i >> 7;            // use i = f*192+jj ordering? keep exact below
    }
    // cwt[jj*64 + f] = ctx_w[f*192 + jj]
    for (int i = tid; i < 64 * 192; i += nt) {
        int jj = i >> 6, f = i & 63;
        g_cwt[jj * 64 + f] = ctx_w[f * 192 + jj];
    }
    // twr[jj*128 + d] = token_w[d*192 + jj]
    for (int i = tid; i < 128 * 192; i += nt) {
        int jj = i >> 7, d = i & 127;
        g_twr[jj * 128 + d] = token_w[d * 192 + jj];
    }
}

// ---------------------------------------------------------------------------
// Kernel 1: per-chunk partial Gram of row-normalized x (unchanged).
// ---------------------------------------------------------------------------
__global__ void __launch_bounds__(256) gram_partial(const float* __restrict__ x) {
    const int b = blockIdx.y;
    const int chunk = blockIdx.x;
    const int rows_per_chunk = Wn / GRAM_CHUNKS;
    const int w_base = chunk * rows_per_chunk;

    __shared__ float xs[64][65];
    __shared__ float sinv2[64];

    const int t = threadIdx.x;
    const int ti = t >> 4;
    const int tj = t & 15;

    float acc[4][4] = {};
    const float* xb = x + (size_t)b * Wn * Fc;

    for (int tile = 0; tile < rows_per_chunk; tile += 64) {
        for (int i = t; i < 64 * 64; i += 256) {
            int r = i >> 6, c = i & 63;
            xs[r][c] = xb[(size_t)(w_base + tile + r) * Fc + c];
        }
        __syncthreads();
        if (t < 64) {
            float s = 0.f;
            #pragma unroll
            for (int c = 0; c < 64; c++) { float v = xs[t][c]; s += v * v; }
            sinv2[t] = 1.0f / s;
        }
        __syncthreads();
        #pragma unroll 4
        for (int w = 0; w < 64; w++) {
            float s = sinv2[w];
            float vi[4], vj[4];
            #pragma unroll
            for (int a = 0; a < 4; a++) vi[a] = xs[w][ti + 16 * a] * s;
            #pragma unroll
            for (int a = 0; a < 4; a++) vj[a] = xs[w][tj + 16 * a];
            #pragma unroll
            for (int a = 0; a < 4; a++)
                #pragma unroll
                for (int c = 0; c < 4; c++) acc[a][c] += vi[a] * vj[c];
        }
        __syncthreads();
    }

    float* dst = g_gram_part + ((size_t)b * GRAM_CHUNKS + chunk) * (Fc * Fc);
    #pragma unroll
    for (int a = 0; a < 4; a++)
        #pragma unroll
        for (int c = 0; c < 4; c++)
            dst[(ti + 16 * a) * 64 + (tj + 16 * c)] = acc[a][c];
}

__global__ void __launch_bounds__(256) gram_reduce() {
    const int b = blockIdx.x;
    const int t = threadIdx.x;
    for (int i = t; i < Fc * Fc; i += 256) {
        float s = 0.f;
        #pragma unroll
        for (int c = 0; c < GRAM_CHUNKS; c++)
            s += g_gram_part[((size_t)b * GRAM_CHUNKS + c) * (Fc * Fc) + i];
        g_gram[b * Fc * Fc + i] = s;
    }
}

// ---------------------------------------------------------------------------
// Kernel H: h = ctxConv(x)+ctx_b + relu(gram@seW + seb)
// CTA = 256 w rows. threads 512 = 8 fgroups x 64 wgroups (w-tile 4, f-tile 8).
// acc packed along f: weights per-lane LDS.128 pairs, x/sew broadcast+dup2.
// ---------------------------------------------------------------------------
#define H_CWT  0                         // 192*64 = 12288
#define H_GRAM 12288                     // 4096
#define XSTR   259
#define H_XT   16384                     // 64*259 = 16576  (x_t[g][j], j=0..257)
#define SSTR   257
#define H_SEWT 32960                     // 64*257 = 16448  (sew_t[g][r], r=0..255)
#define H_TOTALF 49408
#define H_SMEM (H_TOTALF * 4)            // 197632 B

__global__ void __launch_bounds__(512, 1) h_kernel(
    const float* __restrict__ x,
    const float* __restrict__ ctx_b,
    const float* __restrict__ seW_w,
    const float* __restrict__ seW_b)
{
    extern __shared__ float sm[];
    const int b  = blockIdx.y;
    const int w0 = blockIdx.x * 256;
    const int t  = threadIdx.x;
    const float* xb = x + (size_t)b * Wn * Fc;

    // ---- staging (all linear / conflict-free) ----
    for (int i = t; i < 192 * 64; i += 512) sm[H_CWT + i] = g_cwt[i];
    for (int i = t; i < 4096; i += 512)     sm[H_GRAM + i] = g_gram[b * 4096 + i];
    for (int i = t; i < 258 * 64; i += 512) {
        int j = i >> 6, c = i & 63;
        int gr = w0 - 1 + j;
        sm[H_XT + c * XSTR + j] = (gr >= 0 && gr < Wn) ? xb[(size_t)gr * Fc + c] : 0.f;
    }
    for (int i = t; i < 256 * 64; i += 512) {
        int r = i >> 6, c = i & 63;
        sm[H_SEWT + c * SSTR + r] = seW_w[(size_t)(w0 + r) * Fc + c];
    }
    __syncthreads();

    const int fg = t & 7;          // f0 = fg*8
    const int wq = t >> 3;         // wbase = wq*4
    const int f0 = fg * 8;
    const int wbase = wq * 4;

    ull accC[4][4], accS[4][4];
    #pragma unroll
    for (int r = 0; r < 4; r++)
        #pragma unroll
        for (int p = 0; p < 4; p++) { accC[r][p] = 0ull; accS[r][p] = 0ull; }

    unsigned sbase = (unsigned)__cvta_generic_to_shared(sm);
    unsigned cwt_a = sbase + (H_CWT + f0) * 4;
    unsigned gr_a  = sbase + (H_GRAM + f0) * 4;
    const float* xg = sm + H_XT + wbase;
    const float* sg = sm + H_SEWT + wbase;

    #pragma unroll 2
    for (int g = 0; g < 64; g++) {
        // x taps (broadcast within 4-distinct addrs/warp) + dups
        float xv[6];
        #pragma unroll
        for (int j = 0; j < 6; j++) xv[j] = xg[j];
        xg += XSTR;
        // conv: 3 k-steps, weights per-lane LDS.128
        #pragma unroll
        for (int k = 0; k < 3; k++) {
            ull wA, wB;
            lds128p(cwt_a + (unsigned)k * 256, wA, wB);   // f0..f0+3
            ull wC, wD;
            lds128p(cwt_a + (unsigned)k * 256 + 16, wC, wD); // f0+4..f0+7
            #pragma unroll
            for (int r = 0; r < 4; r++) {
                ull a = dup2(xv[r + k]);
                accC[r][0] = ffma2(a, wA, accC[r][0]);
                accC[r][1] = ffma2(a, wB, accC[r][1]);
                accC[r][2] = ffma2(a, wC, accC[r][2]);
                accC[r][3] = ffma2(a, wD, accC[r][3]);
            }
        }
        cwt_a += 768;
        // SE: gram row per-lane, sew broadcast
        {
            ull gA, gB, gC, gD;
            lds128p(gr_a, gA, gB);
            lds128p(gr_a + 16, gC, gD);
            gr_a += 256;
            float sv0 = sg[0], sv1 = sg[1], sv2 = sg[2], sv3 = sg[3];
            sg += SSTR;
            ull s0 = dup2(sv0), s1 = dup2(sv1), s2 = dup2(sv2), s3 = dup2(sv3);
            accS[0][0] = ffma2(s0, gA, accS[0][0]);
            accS[0][1] = ffma2(s0, gB, accS[0][1]);
            accS[0][2] = ffma2(s0, gC, accS[0][2]);
            accS[0][3] = ffma2(s0, gD, accS[0][3]);
            accS[1][0] = ffma2(s1, gA, accS[1][0]);
            accS[1][1] = ffma2(s1, gB, accS[1][1]);
            accS[1][2] = ffma2(s1, gC, accS[1][2]);
            accS[1][3] = ffma2(s1, gD, accS[1][3]);
            accS[2][0] = ffma2(s2, gA, accS[2][0]);
            accS[2][1] = ffma2(s2, gB, accS[2][1]);
            accS[2][2] = ffma2(s2, gC, accS[2][2]);
            accS[2][3] = ffma2(s2, gD, accS[2][3]);
            accS[3][0] = ffma2(s3, gA, accS[3][0]);
            accS[3][1] = ffma2(s3, gB, accS[3][1]);
            accS[3][2] = ffma2(s3, gC, accS[3][2]);
            accS[3][3] = ffma2(s3, gD, accS[3][3]);
        }
    }

    // ---- epilogue ----
    float cb[8];
    #pragma unroll
    for (int j = 0; j < 8; j++) cb[j] = __ldg(ctx_b + f0 + j);
    #pragma unroll
    for (int r = 0; r < 4; r++) {
        float seb = __ldg(seW_b + w0 + wbase + r);
        float o[8];
        #pragma unroll
        for (int p = 0; p < 4; p++) {
            float c0, c1, s0, s1;
            unpack2(accC[r][p], c0, c1);
            unpack2(accS[r][p], s0, s1);
            o[2 * p]     = cb[2 * p]     + c0 + fmaxf(s0 + seb, 0.f);
            o[2 * p + 1] = cb[2 * p + 1] + c1 + fmaxf(s1 + seb, 0.f);
        }
        float* hb = g_h + ((size_t)b * Wn + w0 + wbase + r) * Fc + f0;
        *(float4*)(hb)     = make_float4(o[0], o[1], o[2], o[3]);
        *(float4*)(hb + 4) = make_float4(o[4], o[5], o[6], o[7]);
    }
}

// ---------------------------------------------------------------------------
// Kernel O: out[b,w,d] = sum_{f,k} h[b,(w+k-1)%Wn,f] * token_w[d,f,k]
// CTA = 128 w rows x 128 d. threads 512 = 32 dgroups x 16 wgroups
// (d-tile 4 = 2 dpairs, w-tile 8). acc packed along d.
// ---------------------------------------------------------------------------
#define O_TWR 0                          // 192*128 = 24576
#define HSTR  131
#define O_HT  24576                      // 64*131 = 8384 (h_t[f][j], j=0..129)
#define O_TOTALF 32960
#define O_SMEM (O_TOTALF * 4)            // 131840 B

__global__ void __launch_bounds__(512, 1) out_kernel(float* __restrict__ out)
{
    extern __shared__ float sm[];
    const int b  = blockIdx.y;
    const int w0 = blockIdx.x * 128;
    const int t  = threadIdx.x;

    // ---- staging ----
    for (int i = t; i < 192 * 128; i += 512) sm[O_TWR + i] = g_twr[i];
    const float* hg = g_h + (size_t)b * Wn * Fc;
    for (int i = t; i < 130 * 64; i += 512) {
        int j = i >> 6, c = i & 63;
        int gw = (w0 - 1 + j + Wn) & (Wn - 1);
        sm[O_HT + c * HSTR + j] = hg[(size_t)gw * Fc + c];
    }
    __syncthreads();

    const int dg = t & 31;         // d0 = dg*4
    const int wg = t >> 5;         // wbase = wg*8
    const int d0 = dg * 4;
    const int wbase = wg * 8;

    ull acc[8][2];
    #pragma unroll
    for (int r = 0; r < 8; r++) { acc[r][0] = 0ull; acc[r][1] = 0ull; }

    unsigned sbase = (unsigned)__cvta_generic_to_shared(sm);
    unsigned twr_a = sbase + (O_TWR + d0) * 4;
    const float* hp = sm + O_HT + wbase;

    #pragma unroll 2
    for (int f = 0; f < 64; f++) {
        // 10 h taps (warp-broadcast), dup once each
        ull hd[10];
        #pragma unroll
        for (int j = 0; j < 10; j++) hd[j] = dup2(hp[j]);
        hp += HSTR;
        #pragma unroll
        for (int k = 0; k < 3; k++) {
            ull wA, wB;
            lds128p(twr_a + (unsigned)k * 512, wA, wB);  // d0..d0+3 per lane
            #pragma unroll
            for (int r = 0; r < 8; r++) {
                acc[r][0] = ffma2(hd[r + k], wA, acc[r][0]);
                acc[r][1] = ffma2(hd[r + k], wB, acc[r][1]);
            }
        }
        twr_a += 1536;
    }

    // ---- epilogue: 8 rows x float4, fully coalesced ----
    float* ob = out + ((size_t)b * Wn + w0 + wbase) * Dc + d0;
    #pragma unroll
    for (int r = 0; r < 8; r++) {
        float a0, a1, a2, a3;
        unpack2(acc[r][0], a0, a1);
        unpack2(acc[r][1], a2, a3);
        *(float4*)(ob + (size_t)r * Dc) = make_float4(a0, a1, a2, a3);
    }
}

// ---------------------------------------------------------------------------
extern "C" void kernel_launch(void* const* d_in, const int* in_sizes, int n_in,
                              void* d_out, int out_size) {
    const float* x       = (const float*)d_in[0];
    const float* ctx_w   = (const float*)d_in[1];
    const float* ctx_b   = (const float*)d_in[2];
    const float* token_w = (const float*)d_in[3];
    const float* seW_w   = (const float*)d_in[4];
    const float* seW_b   = (const float*)d_in[5];
    float* out = (float*)d_out;

    cudaFuncSetAttribute(h_kernel,
                         cudaFuncAttributeMaxDynamicSharedMemorySize, H_SMEM);
    cudaFuncSetAttribute(out_kernel,
                         cudaFuncAttributeMaxDynamicSharedMemorySize, O_SMEM);

    transpose_weights<<<48, 256>>>(ctx_w, token_w);
    gram_partial<<<dim3(GRAM_CHUNKS, Bc), 256>>>(x);
    gram_reduce<<<Bc, 256>>>();
    h_kernel<<<dim3(Wn / 256, Bc), 512, H_SMEM>>>(x, ctx_b, seW_w, seW_b);
    out_kernel<<<dim3(Wn / 128, Bc), 512, O_SMEM>>>(out);
}

// round 4
// speedup vs baseline: 1.9954x; 1.3477x over previous
#include <cuda_runtime.h>
#include <cstddef>
#include <cstdint>

#define Bc 48
#define Wn 8192
#define Fc 64
#define Dc 128
#define GRAM_CHUNKS 32

typedef unsigned long long ull;

// device scratch (no runtime allocation allowed)
__device__ float g_gram_part[Bc * GRAM_CHUNKS * Fc * Fc];
__device__ float g_gram[Bc * Fc * Fc];
__device__ float g_h[(size_t)Bc * Wn * Fc];     // 100.7 MB intermediate
__device__ float g_cwt[192 * 64];               // ctx_w transposed  [g*3+k][f]
__device__ float g_twr[192 * 128];              // token_w transposed [f*3+k][d]

// ---------------------------------------------------------------------------
// packed f32x2 helpers
// ---------------------------------------------------------------------------
__device__ __forceinline__ ull pack2(float a, float b) {
    ull r;
    asm("mov.b64 %0, {%1, %2};" : "=l"(r) : "r"(__float_as_uint(a)), "r"(__float_as_uint(b)));
    return r;
}
__device__ __forceinline__ ull dup2(float a) {
    ull r;
    asm("mov.b64 %0, {%1, %1};" : "=l"(r) : "r"(__float_as_uint(a)));
    return r;
}
__device__ __forceinline__ void unpack2(ull v, float& a, float& b) {
    unsigned lo, hi;
    asm("mov.b64 {%0, %1}, %2;" : "=r"(lo), "=r"(hi) : "l"(v));
    a = __uint_as_float(lo); b = __uint_as_float(hi);
}
__device__ __forceinline__ ull ffma2(ull a, ull b, ull c) {
    ull d;
    asm("fma.rn.f32x2 %0, %1, %2, %3;" : "=l"(d) : "l"(a), "l"(b), "l"(c));
    return d;
}
// per-lane 16B shared load -> two packed f32x2
__device__ __forceinline__ void lds128p(unsigned addr, ull& a, ull& b) {
    asm volatile("ld.shared.v2.u64 {%0, %1}, [%2];" : "=l"(a), "=l"(b) : "r"(addr));
}

// ---------------------------------------------------------------------------
// Kernel 0: one-time weight transposes (tiny)
// ---------------------------------------------------------------------------
__global__ void __launch_bounds__(256) transpose_weights(
    const float* __restrict__ ctx_w, const float* __restrict__ token_w) {
    int tid = blockIdx.x * 256 + threadIdx.x;
    int nt = gridDim.x * 256;
    for (int i = tid; i < 64 * 192; i += nt) {
        int jj = i >> 6, f = i & 63;
        g_cwt[jj * 64 + f] = ctx_w[f * 192 + jj];
    }
    for (int i = tid; i < 128 * 192; i += nt) {
        int jj = i >> 7, d = i & 127;
        g_twr[jj * 128 + d] = token_w[d * 192 + jj];
    }
}

// ---------------------------------------------------------------------------
// Kernel 1: per-chunk partial Gram (FFMA2, parallel norm).
// gram[b,i,j] = sum_w x[b,w,i]*x[b,w,j] / ||x[b,w,:]||^2
// ---------------------------------------------------------------------------
__global__ void __launch_bounds__(256) gram_partial(const float* __restrict__ x) {
    const int b = blockIdx.y;
    const int chunk = blockIdx.x;
    const int w_base = chunk * (Wn / GRAM_CHUNKS);

    __shared__ float xs[64][66];     // even stride: LDS.64 aligned
    __shared__ float npart[4][64];
    __shared__ float sinv2[64];

    const int t = threadIdx.x;
    const int ti = t >> 4;   // 0..15
    const int tj = t & 15;   // 0..15

    ull acc[4][2];
    #pragma unroll
    for (int a = 0; a < 4; a++) { acc[a][0] = 0ull; acc[a][1] = 0ull; }

    const float* xb = x + (size_t)b * Wn * Fc;

    for (int tile = 0; tile < 256; tile += 64) {
        for (int i = t; i < 64 * 64; i += 256) {
            int r = i >> 6, c = i & 63;
            xs[r][c] = xb[(size_t)(w_base + tile + r) * Fc + c];
        }
        __syncthreads();
        {   // parallel norm: 4 threads per row
            int q = t >> 6, r = t & 63;
            float s = 0.f;
            #pragma unroll
            for (int c = 0; c < 16; c++) { float v = xs[r][q * 16 + c]; s += v * v; }
            npart[q][r] = s;
        }
        __syncthreads();
        if (t < 64)
            sinv2[t] = 1.0f / (npart[0][t] + npart[1][t] + npart[2][t] + npart[3][t]);
        __syncthreads();

        #pragma unroll 4
        for (int w = 0; w < 64; w++) {
            float s = sinv2[w];
            const ull* row = (const ull*)(&xs[w][0]);
            ull vj0 = row[tj], vj1 = row[tj + 16];
            float vi0 = xs[w][ti] * s,      vi1 = xs[w][ti + 16] * s;
            float vi2 = xs[w][ti + 32] * s, vi3 = xs[w][ti + 48] * s;
            acc[0][0] = ffma2(dup2(vi0), vj0, acc[0][0]);
            acc[0][1] = ffma2(dup2(vi0), vj1, acc[0][1]);
            acc[1][0] = ffma2(dup2(vi1), vj0, acc[1][0]);
            acc[1][1] = ffma2(dup2(vi1), vj1, acc[1][1]);
            acc[2][0] = ffma2(dup2(vi2), vj0, acc[2][0]);
            acc[2][1] = ffma2(dup2(vi2), vj1, acc[2][1]);
            acc[3][0] = ffma2(dup2(vi3), vj0, acc[3][0]);
            acc[3][1] = ffma2(dup2(vi3), vj1, acc[3][1]);
        }
        __syncthreads();
    }

    float* dst = g_gram_part + ((size_t)b * GRAM_CHUNKS + chunk) * (Fc * Fc);
    #pragma unroll
    for (int a = 0; a < 4; a++)
        #pragma unroll
        for (int c = 0; c < 2; c++) {
            float u, v;
            unpack2(acc[a][c], u, v);
            *(float2*)(dst + (ti + 16 * a) * 64 + 2 * (tj + 16 * c)) = make_float2(u, v);
        }
}

__global__ void __launch_bounds__(256) gram_reduce() {
    const int b = blockIdx.x;
    const int t = threadIdx.x;
    for (int i = t; i < Fc * Fc; i += 256) {
        float s = 0.f;
        #pragma unroll
        for (int c = 0; c < GRAM_CHUNKS; c++)
            s += g_gram_part[((size_t)b * GRAM_CHUNKS + c) * (Fc * Fc) + i];
        g_gram[b * Fc * Fc + i] = s;
    }
}

// ---------------------------------------------------------------------------
// Kernel H: h = ctxConv(x)+ctx_b + relu(gram@seW + seb)
// CTA = 256 w x 64 f, 512 threads = 32 wgroups (T_w=8) x 16 fgroups (T_f=2 pairs).
// TWO PASSES over g sharing one accumulator set: SE -> relu+bias -> conv.
// ---------------------------------------------------------------------------
#define H_CWT  0                         // 12288
#define H_GRAM 12288                     // 4096
#define XSTR   260
#define H_XT   16384                     // 64*260 = 16640 (x_t[g][j], j=0..257)
#define SSTR   258
#define H_SEWT 33024                     // 64*258 = 16512 (sew_t[g][r], r=0..255)
#define H_TOTALF 49536
#define H_SMEM (H_TOTALF * 4)            // 198144 B

__global__ void __launch_bounds__(512, 1) h_kernel(
    const float* __restrict__ x,
    const float* __restrict__ ctx_b,
    const float* __restrict__ seW_w,
    const float* __restrict__ seW_b)
{
    extern __shared__ float sm[];
    const int b  = blockIdx.y;
    const int w0 = blockIdx.x * 256;
    const int t  = threadIdx.x;
    const float* xb = x + (size_t)b * Wn * Fc;

    // ---- staging ----
    for (int i = t; i < 192 * 64; i += 512) sm[H_CWT + i] = g_cwt[i];
    for (int i = t; i < 4096; i += 512)     sm[H_GRAM + i] = g_gram[b * 4096 + i];
    for (int i = t; i < 258 * 64; i += 512) {
        int j = i >> 6, c = i & 63;
        int gr = w0 - 1 + j;
        sm[H_XT + c * XSTR + j] = (gr >= 0 && gr < Wn) ? xb[(size_t)gr * Fc + c] : 0.f;
    }
    for (int i = t; i < 256 * 64; i += 512) {
        int r = i >> 6, c = i & 63;
        sm[H_SEWT + c * SSTR + r] = seW_w[(size_t)(w0 + r) * Fc + c];
    }
    __syncthreads();

    const int fg = t & 15;         // f0 = fg*4 (2 pairs)
    const int wq = t >> 4;         // wbase = wq*8
    const int f0 = fg * 4;
    const int wbase = wq * 8;

    ull acc[8][2];
    #pragma unroll
    for (int r = 0; r < 8; r++) { acc[r][0] = 0ull; acc[r][1] = 0ull; }

    unsigned sbase = (unsigned)__cvta_generic_to_shared(sm);

    // ======== pass 1: SE = gram @ seW ========
    {
        unsigned gr_a = sbase + (H_GRAM + f0) * 4;
        const float2* sp = (const float2*)(sm + H_SEWT + wbase);  // stride 129 float2
        #pragma unroll 2
        for (int g = 0; g < 64; g++) {
            ull gA, gB;
            lds128p(gr_a, gA, gB);
            gr_a += 256;
            float2 s01 = sp[0], s23 = sp[1], s45 = sp[2], s67 = sp[3];
            sp += SSTR / 2;
            ull d0 = dup2(s01.x), d1 = dup2(s01.y), d2 = dup2(s23.x), d3 = dup2(s23.y);
            ull d4 = dup2(s45.x), d5 = dup2(s45.y), d6 = dup2(s67.x), d7 = dup2(s67.y);
            acc[0][0] = ffma2(d0, gA, acc[0][0]); acc[0][1] = ffma2(d0, gB, acc[0][1]);
            acc[1][0] = ffma2(d1, gA, acc[1][0]); acc[1][1] = ffma2(d1, gB, acc[1][1]);
            acc[2][0] = ffma2(d2, gA, acc[2][0]); acc[2][1] = ffma2(d2, gB, acc[2][1]);
            acc[3][0] = ffma2(d3, gA, acc[3][0]); acc[3][1] = ffma2(d3, gB, acc[3][1]);
            acc[4][0] = ffma2(d4, gA, acc[4][0]); acc[4][1] = ffma2(d4, gB, acc[4][1]);
            acc[5][0] = ffma2(d5, gA, acc[5][0]); acc[5][1] = ffma2(d5, gB, acc[5][1]);
            acc[6][0] = ffma2(d6, gA, acc[6][0]); acc[6][1] = ffma2(d6, gB, acc[6][1]);
            acc[7][0] = ffma2(d7, gA, acc[7][0]); acc[7][1] = ffma2(d7, gB, acc[7][1]);
        }
    }

    // ======== relu + fold biases into acc ========
    {
        float cb0 = __ldg(ctx_b + f0),     cb1 = __ldg(ctx_b + f0 + 1);
        float cb2 = __ldg(ctx_b + f0 + 2), cb3 = __ldg(ctx_b + f0 + 3);
        #pragma unroll
        for (int r = 0; r < 8; r++) {
            float seb = __ldg(seW_b + w0 + wbase + r);
            float u, v;
            unpack2(acc[r][0], u, v);
            acc[r][0] = pack2(fmaxf(u + seb, 0.f) + cb0, fmaxf(v + seb, 0.f) + cb1);
            unpack2(acc[r][1], u, v);
            acc[r][1] = pack2(fmaxf(u + seb, 0.f) + cb2, fmaxf(v + seb, 0.f) + cb3);
        }
    }

    // ======== pass 2: += contextConv ========
    {
        unsigned cwt_a = sbase + (H_CWT + f0) * 4;
        const float2* xp = (const float2*)(sm + H_XT + wbase);    // stride 130 float2
        #pragma unroll 2
        for (int g = 0; g < 64; g++) {
            float2 p0 = xp[0], p1 = xp[1], p2 = xp[2], p3 = xp[3], p4 = xp[4];
            xp += XSTR / 2;
            ull xd[10];
            xd[0] = dup2(p0.x); xd[1] = dup2(p0.y);
            xd[2] = dup2(p1.x); xd[3] = dup2(p1.y);
            xd[4] = dup2(p2.x); xd[5] = dup2(p2.y);
            xd[6] = dup2(p3.x); xd[7] = dup2(p3.y);
            xd[8] = dup2(p4.x); xd[9] = dup2(p4.y);
            #pragma unroll
            for (int k = 0; k < 3; k++) {
                ull wA, wB;
                lds128p(cwt_a + (unsigned)k * 256, wA, wB);
                #pragma unroll
                for (int r = 0; r < 8; r++) {
                    acc[r][0] = ffma2(xd[r + k], wA, acc[r][0]);
                    acc[r][1] = ffma2(xd[r + k], wB, acc[r][1]);
                }
            }
            cwt_a += 768;
        }
    }

    // ---- store ----
    #pragma unroll
    for (int r = 0; r < 8; r++) {
        float o0, o1, o2, o3;
        unpack2(acc[r][0], o0, o1);
        unpack2(acc[r][1], o2, o3);
        *(float4*)(g_h + ((size_t)b * Wn + w0 + wbase + r) * Fc + f0) =
            make_float4(o0, o1, o2, o3);
    }
}

// ---------------------------------------------------------------------------
// Kernel O: out[b,w,d] = sum_{f,k} h[b,(w+k-1)%Wn,f] * token_w[d,f,k]
// CTA = 256 w x 128 d, 512 threads = 32 wgroups (T_w=8) x 16 dgroups (T_f=4 pairs).
// ---------------------------------------------------------------------------
#define O_TWR 0                          // 24576
#define HSTR  260
#define O_HT  24576                      // 64*260 = 16640 (h_t[f][j], j=0..257)
#define O_TOTALF 41216
#define O_SMEM (O_TOTALF * 4)            // 164864 B

__global__ void __launch_bounds__(512, 1) out_kernel(float* __restrict__ out)
{
    extern __shared__ float sm[];
    const int b  = blockIdx.y;
    const int w0 = blockIdx.x * 256;
    const int t  = threadIdx.x;

    for (int i = t; i < 192 * 128; i += 512) sm[O_TWR + i] = g_twr[i];
    const float* hg = g_h + (size_t)b * Wn * Fc;
    for (int i = t; i < 258 * 64; i += 512) {
        int j = i >> 6, c = i & 63;
        int gw = (w0 - 1 + j + Wn) & (Wn - 1);
        sm[O_HT + c * HSTR + j] = hg[(size_t)gw * Fc + c];
    }
    __syncthreads();

    const int dg = t & 15;         // d0 = dg*8 (4 pairs)
    const int wq = t >> 4;         // wbase = wq*8
    const int d0 = dg * 8;
    const int wbase = wq * 8;

    ull acc[8][4];
    #pragma unroll
    for (int r = 0; r < 8; r++)
        #pragma unroll
        for (int p = 0; p < 4; p++) acc[r][p] = 0ull;

    unsigned sbase = (unsigned)__cvta_generic_to_shared(sm);
    unsigned twr_a = sbase + (O_TWR + d0) * 4;
    const float2* hp = (const float2*)(sm + O_HT + wbase);  // stride 130 float2

    #pragma unroll 2
    for (int f = 0; f < 64; f++) {
        float2 p0 = hp[0], p1 = hp[1], p2 = hp[2], p3 = hp[3], p4 = hp[4];
        hp += HSTR / 2;
        ull hd[10];
        hd[0] = dup2(p0.x); hd[1] = dup2(p0.y);
        hd[2] = dup2(p1.x); hd[3] = dup2(p1.y);
        hd[4] = dup2(p2.x); hd[5] = dup2(p2.y);
        hd[6] = dup2(p3.x); hd[7] = dup2(p3.y);
        hd[8] = dup2(p4.x); hd[9] = dup2(p4.y);
        #pragma unroll
        for (int k = 0; k < 3; k++) {
            ull wA, wB, wC, wD;
            unsigned a = twr_a + (unsigned)k * 512;
            lds128p(a, wA, wB);
            lds128p(a + 16, wC, wD);
            #pragma unroll
            for (int r = 0; r < 8; r++) {
                acc[r][0] = ffma2(hd[r + k], wA, acc[r][0]);
                acc[r][1] = ffma2(hd[r + k], wB, acc[r][1]);
                acc[r][2] = ffma2(hd[r + k], wC, acc[r][2]);
                acc[r][3] = ffma2(hd[r + k], wD, acc[r][3]);
            }
        }
        twr_a += 1536;
    }

    #pragma unroll
    for (int r = 0; r < 8; r++) {
        float a0, a1, a2, a3, a4, a5, a6, a7;
        unpack2(acc[r][0], a0, a1);
        unpack2(acc[r][1], a2, a3);
        unpack2(acc[r][2], a4, a5);
        unpack2(acc[r][3], a6, a7);
        float* ob = out + ((size_t)b * Wn + w0 + wbase + r) * Dc + d0;
        *(float4*)(ob)     = make_float4(a0, a1, a2, a3);
        *(float4*)(ob + 4) = make_float4(a4, a5, a6, a7);
    }
}

// ---------------------------------------------------------------------------
extern "C" void kernel_launch(void* const* d_in, const int* in_sizes, int n_in,
                              void* d_out, int out_size) {
    const float* x       = (const float*)d_in[0];
    const float* ctx_w   = (const float*)d_in[1];
    const float* ctx_b   = (const float*)d_in[2];
    const float* token_w = (const float*)d_in[3];
    const float* seW_w   = (const float*)d_in[4];
    const float* seW_b   = (const float*)d_in[5];
    float* out = (float*)d_out;

    cudaFuncSetAttribute(h_kernel,
                         cudaFuncAttributeMaxDynamicSharedMemorySize, H_SMEM);
    cudaFuncSetAttribute(out_kernel,
                         cudaFuncAttributeMaxDynamicSharedMemorySize, O_SMEM);

    transpose_weights<<<48, 256>>>(ctx_w, token_w);
    gram_partial<<<dim3(GRAM_CHUNKS, Bc), 256>>>(x);
    gram_reduce<<<Bc, 256>>>();
    h_kernel<<<dim3(Wn / 256, Bc), 512, H_SMEM>>>(x, ctx_b, seW_w, seW_b);
    out_kernel<<<dim3(Wn / 256, Bc), 512, O_SMEM>>>(out);
}